// round 1
// baseline (speedup 1.0000x reference)
#include <cuda_runtime.h>
#include <math.h>

// ---------------- problem constants ----------------
#define NB 16      // batch
#define NT 4096    // tokens
#define HH 1024    // hidden
#define NS 16      // segments
#define NP 6       // plan slots
#define NHEAD 8
#define DHD 128    // head dim
#define PLAN_ELEMS (NB*NP*HH)   // 98304

// ---------------- device scratch (static, no allocs) ----------------
__device__ int   g_bounds[NB*(NS+1)];
__device__ float g_poolpart[4*NB*NS*HH];      // 1M floats
__device__ float g_seg0[NB*NS*HH];
__device__ float g_qkv[NB*NS*3*HH];
__device__ float g_o[NB*NS*HH];
__device__ float g_tmp[NB*NS*HH];
__device__ float g_seg1[NB*NS*HH];
__device__ float g_hbuf[NB*NS*HH];
__device__ float g_logits[NB*NS];
__device__ float g_sal[NB*NS];
__device__ float g_wseg[NB*NS*HH];
__device__ float g_qh[NP*HH];
__device__ float g_kv[NB*NS*2*HH];
__device__ float g_o2[NB*NP*HH];
__device__ float g_plan[NB*NP*HH];
__device__ float g_y[NB*NP*HH];
__device__ float g_qkvr[NB*NP*3*HH];
__device__ float g_o3[NB*NP*HH];
__device__ float g_ffn[NB*NP*4*HH];
__device__ float g_part[2*1024*1024];          // split-K partials (max 1.57M used)
__device__ float g_entpart[NB];
__device__ float g_redpart[NB];

// ---------------- lengths + segment bounds ----------------
__global__ void lengths_kernel(const int* __restrict__ mask) {
    int b = blockIdx.x;
    __shared__ int red[256];
    int t = threadIdx.x;
    int s = 0;
    for (int i = t; i < NT; i += 256) s += mask[b*NT + i];
    red[t] = s; __syncthreads();
    for (int o = 128; o > 0; o >>= 1) { if (t < o) red[t] += red[t+o]; __syncthreads(); }
    if (t == 0) {
        int L = red[0];
        for (int k = 0; k <= NS; k++) g_bounds[b*(NS+1) + k] = (k * L) / NS;  // exact (div by 16)
    }
}

// ---------------- segment pooling (split over 4 row-slices) ----------------
__global__ void segpool_partial(const float* __restrict__ ts) {
    int seg = blockIdx.x;            // 0..255
    int b = seg >> 4, s = seg & 15;
    int slice = blockIdx.y;          // 0..3
    int lo = g_bounds[b*(NS+1) + s], hi = g_bounds[b*(NS+1) + s + 1];
    int cnt = hi - lo;
    int chunk = (cnt + 3) >> 2;
    int r0 = lo + slice * chunk;
    int r1 = min(hi, r0 + chunk);
    int t = threadIdx.x;             // 256 threads, 4 cols each
    float4 acc = make_float4(0.f,0.f,0.f,0.f);
    const float* base = ts + (size_t)b * NT * HH;
    for (int r = r0; r < r1; r++) {
        float4 v = *(const float4*)(base + (size_t)r * HH + t * 4);
        acc.x += v.x; acc.y += v.y; acc.z += v.z; acc.w += v.w;
    }
    *(float4*)&g_poolpart[((size_t)slice * NB*NS + seg) * HH + t * 4] = acc;
}

__global__ void segpool_finish() {
    int idx = blockIdx.x * 256 + threadIdx.x;   // < 262144
    int seg = idx >> 10;
    int b = seg >> 4, s = seg & 15;
    float cnt = (float)(g_bounds[b*(NS+1)+s+1] - g_bounds[b*(NS+1)+s]);
    const int ST = NB*NS*HH;
    float v = g_poolpart[idx] + g_poolpart[ST + idx] + g_poolpart[2*ST + idx] + g_poolpart[3*ST + idx];
    g_seg0[idx] = v / fmaxf(cnt, 1.f);
}

// ---------------- generic split-K GEMM: P[z] = A[M,K] @ W[N,K]^T (K-slice z) ----------------
__global__ void __launch_bounds__(256) gemm_part_kernel(
    const float* __restrict__ A, const float* __restrict__ W,
    float* __restrict__ P, int M, int N, int K, int kslices)
{
    __shared__ float As[16][64];
    __shared__ float Ws[16][64];
    int m0 = blockIdx.x * 64;
    int n0 = blockIdx.y * 64;
    int Kper = K / kslices;
    int k0 = blockIdx.z * Kper;
    int tid = threadIdx.x;
    int tx = tid & 15, ty = tid >> 4;
    int lr = tid >> 2;
    int lk = (tid & 3) << 2;
    float acc[4][4];
#pragma unroll
    for (int i = 0; i < 4; i++)
#pragma unroll
        for (int j = 0; j < 4; j++) acc[i][j] = 0.f;

    for (int kt = 0; kt < Kper; kt += 16) {
        int kb = k0 + kt;
        float4 va = make_float4(0.f,0.f,0.f,0.f);
        int gm = m0 + lr;
        if (gm < M) va = *(const float4*)(A + (size_t)gm * K + kb + lk);
        float4 vw = make_float4(0.f,0.f,0.f,0.f);
        int gn = n0 + lr;
        if (gn < N) vw = *(const float4*)(W + (size_t)gn * K + kb + lk);
        As[lk+0][lr] = va.x; As[lk+1][lr] = va.y; As[lk+2][lr] = va.z; As[lk+3][lr] = va.w;
        Ws[lk+0][lr] = vw.x; Ws[lk+1][lr] = vw.y; Ws[lk+2][lr] = vw.z; Ws[lk+3][lr] = vw.w;
        __syncthreads();
#pragma unroll
        for (int k = 0; k < 16; k++) {
            float a[4], b[4];
            *(float4*)a = *(const float4*)&As[k][ty*4];
            *(float4*)b = *(const float4*)&Ws[k][tx*4];
#pragma unroll
            for (int i = 0; i < 4; i++)
#pragma unroll
                for (int j = 0; j < 4; j++) acc[i][j] = fmaf(a[i], b[j], acc[i][j]);
        }
        __syncthreads();
    }
    size_t base = (size_t)blockIdx.z * M * N;
#pragma unroll
    for (int i = 0; i < 4; i++) {
        int m = m0 + ty*4 + i;
        if (m >= M) continue;
#pragma unroll
        for (int j = 0; j < 4; j++) {
            int n = n0 + tx*4 + j;
            if (n < N) P[base + (size_t)m * N + n] = acc[i][j];
        }
    }
}

// epilogue: out = [gelu]( sum_z P[z] + bias ) [+ res]
__global__ void epilogue_kernel(const float* __restrict__ P, const float* __restrict__ bias,
                                const float* __restrict__ res, float* __restrict__ out,
                                int M, int N, int kslices, int gelu)
{
    int idx = blockIdx.x * 256 + threadIdx.x;
    if (idx >= M * N) return;
    int n = idx % N;
    float v = 0.f;
    size_t MN = (size_t)M * N;
    for (int s = 0; s < kslices; s++) v += P[(size_t)s * MN + idx];
    v += bias[n];
    if (gelu) v = 0.5f * v * (1.f + erff(v * 0.70710678118654752f));
    if (res) v += res[idx];
    out[idx] = v;
}

// ---------------- generic small attention: one (b, head) per block ----------------
__global__ void attn_kernel(const float* __restrict__ qb, const float* __restrict__ kb,
                            const float* __restrict__ vb, float* __restrict__ ob,
                            int NQ, int NK,
                            int qRowStr, long long qBatStr,
                            int kRowStr, long long kBatStr,
                            int vRowStr, long long vBatStr,
                            int oRowStr, long long oBatStr)
{
    int b = blockIdx.x, h = blockIdx.y;
    const float* q = qb + b * qBatStr + h * DHD;
    const float* k = kb + b * kBatStr + h * DHD;
    const float* v = vb + b * vBatStr + h * DHD;
    float* o = ob + b * oBatStr + h * DHD;
    __shared__ float qs[16][DHD+1], ks[16][DHD+1], vs[16][DHD+1];
    __shared__ float pr[16][17];
    int t = threadIdx.x;  // 128
    for (int i = 0; i < NQ; i++) qs[i][t] = q[(size_t)i * qRowStr + t];
    for (int i = 0; i < NK; i++) { ks[i][t] = k[(size_t)i * kRowStr + t]; vs[i][t] = v[(size_t)i * vRowStr + t]; }
    __syncthreads();
    const float scale = 0.08838834764831843f;   // 1/sqrt(128)
    for (int p = t; p < NQ * NK; p += 128) {
        int qi = p / NK, ki = p - qi * NK;
        float acc = 0.f;
#pragma unroll 4
        for (int d = 0; d < DHD; d++) acc = fmaf(qs[qi][d], ks[ki][d], acc);
        pr[qi][ki] = acc * scale;
    }
    __syncthreads();
    if (t < NQ) {
        float mx = -1e30f;
        for (int kk = 0; kk < NK; kk++) mx = fmaxf(mx, pr[t][kk]);
        float sm = 0.f;
        for (int kk = 0; kk < NK; kk++) { float e = expf(pr[t][kk] - mx); pr[t][kk] = e; sm += e; }
        float inv = 1.f / sm;
        for (int kk = 0; kk < NK; kk++) pr[t][kk] *= inv;
    }
    __syncthreads();
    for (int j = t; j < NQ * DHD; j += 128) {
        int qi = j >> 7, d = j & 127;
        float acc = 0.f;
        for (int kk = 0; kk < NK; kk++) acc = fmaf(pr[qi][kk], vs[kk][d], acc);
        o[(size_t)qi * oRowStr + d] = acc;
    }
}

// ---------------- layernorm (two-pass, row per block) ----------------
__global__ void ln_kernel(const float* __restrict__ x,
                          const float* __restrict__ g, const float* __restrict__ be,
                          float* __restrict__ out)
{
    int r = blockIdx.x, t = threadIdx.x;   // 256 threads
    __shared__ float xs[HH];
    __shared__ float red[256];
    const float* xr = x + (size_t)r * HH;
    float s = 0.f;
    for (int i = t; i < HH; i += 256) { float v = xr[i]; xs[i] = v; s += v; }
    red[t] = s; __syncthreads();
    for (int o = 128; o > 0; o >>= 1) { if (t < o) red[t] += red[t+o]; __syncthreads(); }
    float mean = red[0] * (1.f / HH);
    __syncthreads();
    float s2 = 0.f;
    for (int i = t; i < HH; i += 256) { float d = xs[i] - mean; s2 += d * d; }
    red[t] = s2; __syncthreads();
    for (int o = 128; o > 0; o >>= 1) { if (t < o) red[t] += red[t+o]; __syncthreads(); }
    float inv = rsqrtf(red[0] * (1.f / HH) + 1e-5f);
    for (int i = t; i < HH; i += 256)
        out[(size_t)r * HH + i] = (xs[i] - mean) * inv * g[i] + be[i];
}

// ---------------- salience logits (dot with sal_w2) ----------------
__global__ void logits_kernel(const float* __restrict__ hbuf, const float* __restrict__ w,
                              const float* __restrict__ b2)
{
    int r = blockIdx.x, t = threadIdx.x;  // 128
    __shared__ float red[128];
    float s = 0.f;
    for (int i = t; i < HH; i += 128) s = fmaf(hbuf[(size_t)r * HH + i], w[i], s);
    red[t] = s; __syncthreads();
    for (int o = 64; o > 0; o >>= 1) { if (t < o) red[t] += red[t+o]; __syncthreads(); }
    if (t == 0) g_logits[r] = red[0] + b2[0];
}

// ---------------- salience softmax + entropy + weighted segments ----------------
__global__ void salience_kernel() {
    int b = blockIdx.x, t = threadIdx.x;  // 256
    __shared__ float sal_s[NS];
    if (t == 0) {
        float mx = -1e30f;
        for (int s = 0; s < NS; s++) mx = fmaxf(mx, g_logits[b*NS + s]);
        float sm = 0.f;
        for (int s = 0; s < NS; s++) { float e = expf(g_logits[b*NS + s] - mx); sal_s[s] = e; sm += e; }
        float inv = 1.f / sm, ent = 0.f;
        for (int s = 0; s < NS; s++) {
            sal_s[s] *= inv;
            g_sal[b*NS + s] = sal_s[s];
            ent -= sal_s[s] * logf(sal_s[s] + 1e-8f);
        }
        g_entpart[b] = ent;
    }
    __syncthreads();
    for (int i = t; i < NS * HH; i += 256) {
        int s = i >> 10;
        g_wseg[(size_t)b * NS * HH + i] = g_seg1[(size_t)b * NS * HH + i] * sal_s[s];
    }
}

// ---------------- redundancy ----------------
__global__ void red_kernel() {
    int b = blockIdx.x, t = threadIdx.x;  // 128
    __shared__ float ps[NP][HH+1];
    __shared__ float nrm[NP];
    __shared__ float parr[16];
    for (int i = t; i < NP * HH; i += 128) ps[i >> 10][i & 1023] = g_plan[(size_t)b * NP * HH + i];
    __syncthreads();
    if (t < NP) {
        float s = 0.f;
        for (int d = 0; d < HH; d++) s = fmaf(ps[t][d], ps[t][d], s);
        nrm[t] = fmaxf(sqrtf(s), 1e-12f);
    }
    __syncthreads();
    if (t < 15) {
        int i = 0, j = 0, c = t;
        for (i = 0; i < NP; i++) { int row = NP - 1 - i; if (c < row) { j = i + 1 + c; break; } c -= row; }
        float s = 0.f;
        for (int d = 0; d < HH; d++) s = fmaf(ps[i][d], ps[j][d], s);
        float sim = s / (nrm[i] * nrm[j]);
        parr[t] = 2.f * sim * sim;
    }
    __syncthreads();
    if (t == 0) {
        float s = 0.f;
        for (int p = 0; p < 15; p++) s += parr[p];
        g_redpart[b] = s;
    }
}

// ---------------- output assembly ----------------
__global__ void copy_plan_kernel(float* __restrict__ out, int n) {
    int i = blockIdx.x * 256 + threadIdx.x;
    if (i < n) out[i] = g_plan[i];
}

__global__ void finalize_kernel(float* __restrict__ out, int out_size) {
    int t = threadIdx.x;  // 256
    if (PLAN_ELEMS + t < out_size && t < NB*NS) out[PLAN_ELEMS + t] = g_sal[t];
    if (t == 0) {
        if (PLAN_ELEMS + 256 < out_size) {
            float e = 0.f;
            for (int b = 0; b < NB; b++) e += g_entpart[b];
            out[PLAN_ELEMS + 256] = e / (float)NB;
        }
        if (PLAN_ELEMS + 257 < out_size) {
            float r = 0.f;
            for (int b = 0; b < NB; b++) r += g_redpart[b];
            out[PLAN_ELEMS + 257] = r / (float)(NB * NP * (NP - 1));
        }
    }
}

// ---------------- host helper ----------------
static void run_gemm(const float* A, const float* W, int M, int N, int K, int ks,
                     const float* bias, const float* res, float* out, int gelu, float* part)
{
    dim3 grid((M + 63) / 64, (N + 63) / 64, ks);
    gemm_part_kernel<<<grid, 256>>>(A, W, part, M, N, K, ks);
    int tot = M * N;
    epilogue_kernel<<<(tot + 255) / 256, 256>>>(part, bias, res, out, M, N, ks, gelu);
}

extern "C" void kernel_launch(void* const* d_in, const int* in_sizes, int n_in,
                              void* d_out, int out_size)
{
    const float* ts       = (const float*)d_in[0];
    const int*   mask     = (const int*)  d_in[1];
    const float* sa_in_w  = (const float*)d_in[2];
    const float* sa_in_b  = (const float*)d_in[3];
    const float* sa_out_w = (const float*)d_in[4];
    const float* sa_out_b = (const float*)d_in[5];
    const float* ln_g     = (const float*)d_in[6];
    const float* ln_b     = (const float*)d_in[7];
    const float* sal_w1   = (const float*)d_in[8];
    const float* sal_b1   = (const float*)d_in[9];
    const float* sal_w2   = (const float*)d_in[10];
    const float* sal_b2   = (const float*)d_in[11];
    const float* plan_q   = (const float*)d_in[12];
    const float* qa_in_w  = (const float*)d_in[13];
    const float* qa_in_b  = (const float*)d_in[14];
    const float* qa_out_w = (const float*)d_in[15];
    const float* qa_out_b = (const float*)d_in[16];
    const float* r_in_w   = (const float*)d_in[17];
    const float* r_in_b   = (const float*)d_in[18];
    const float* r_out_w  = (const float*)d_in[19];
    const float* r_out_b  = (const float*)d_in[20];
    const float* r_ln1_g  = (const float*)d_in[21];
    const float* r_ln1_b  = (const float*)d_in[22];
    const float* r_ln2_g  = (const float*)d_in[23];
    const float* r_ln2_b  = (const float*)d_in[24];
    const float* r_w1     = (const float*)d_in[25];
    const float* r_b1     = (const float*)d_in[26];
    const float* r_w2     = (const float*)d_in[27];
    const float* r_b2     = (const float*)d_in[28];
    float* out = (float*)d_out;

    float *p_part, *p_seg0, *p_qkv, *p_o, *p_tmp, *p_seg1, *p_h, *p_qh, *p_kv,
          *p_o2, *p_plan, *p_y, *p_qkvr, *p_o3, *p_ffn, *p_wseg;
    cudaGetSymbolAddress((void**)&p_part, g_part);
    cudaGetSymbolAddress((void**)&p_seg0, g_seg0);
    cudaGetSymbolAddress((void**)&p_qkv,  g_qkv);
    cudaGetSymbolAddress((void**)&p_o,    g_o);
    cudaGetSymbolAddress((void**)&p_tmp,  g_tmp);
    cudaGetSymbolAddress((void**)&p_seg1, g_seg1);
    cudaGetSymbolAddress((void**)&p_h,    g_hbuf);
    cudaGetSymbolAddress((void**)&p_qh,   g_qh);
    cudaGetSymbolAddress((void**)&p_kv,   g_kv);
    cudaGetSymbolAddress((void**)&p_o2,   g_o2);
    cudaGetSymbolAddress((void**)&p_plan, g_plan);
    cudaGetSymbolAddress((void**)&p_y,    g_y);
    cudaGetSymbolAddress((void**)&p_qkvr, g_qkvr);
    cudaGetSymbolAddress((void**)&p_o3,   g_o3);
    cudaGetSymbolAddress((void**)&p_ffn,  g_ffn);
    cudaGetSymbolAddress((void**)&p_wseg, g_wseg);

    // 1) lengths + bounds, segment pooling
    lengths_kernel<<<16, 256>>>(mask);
    segpool_partial<<<dim3(NB*NS, 4), 256>>>(ts);
    segpool_finish<<<(NB*NS*HH)/256, 256>>>();

    // 2) segment self-attention
    run_gemm(p_seg0, sa_in_w, 256, 3*HH, HH, 2, sa_in_b, nullptr, p_qkv, 0, p_part);
    attn_kernel<<<dim3(NB, NHEAD), 128>>>(p_qkv, p_qkv + HH, p_qkv + 2*HH, p_o,
                                          16, 16,
                                          3*HH, (long long)NS*3*HH,
                                          3*HH, (long long)NS*3*HH,
                                          3*HH, (long long)NS*3*HH,
                                          HH,   (long long)NS*HH);
    run_gemm(p_o, sa_out_w, 256, HH, HH, 2, sa_out_b, p_seg0, p_tmp, 0, p_part);
    ln_kernel<<<256, 256>>>(p_tmp, ln_g, ln_b, p_seg1);

    // 3) salience
    run_gemm(p_seg1, sal_w1, 256, HH, HH, 2, sal_b1, nullptr, p_h, 1, p_part);
    logits_kernel<<<256, 128>>>(p_h, sal_w2, sal_b2);
    salience_kernel<<<16, 256>>>();

    // 4) plan cross-attention (qh is batch-independent)
    run_gemm(plan_q, qa_in_w, NP, HH, HH, 8, qa_in_b, nullptr, p_qh, 0, p_part);
    run_gemm(p_wseg, qa_in_w + (size_t)HH*HH, 256, 2*HH, HH, 2, qa_in_b + HH, nullptr, p_kv, 0, p_part);
    attn_kernel<<<dim3(NB, NHEAD), 128>>>(p_qh, p_kv, p_kv + HH, p_o2,
                                          NP, 16,
                                          HH,   0LL,
                                          2*HH, (long long)NS*2*HH,
                                          2*HH, (long long)NS*2*HH,
                                          HH,   (long long)NP*HH);
    run_gemm(p_o2, qa_out_w, NB*NP, HH, HH, 4, qa_out_b, nullptr, p_plan, 0, p_part);

    // 5) refinement transformer layers (norm_first)
    for (int l = 0; l < 2; l++) {
        ln_kernel<<<NB*NP, 256>>>(p_plan, r_ln1_g + l*HH, r_ln1_b + l*HH, p_y);
        run_gemm(p_y, r_in_w + (size_t)l*3*HH*HH, NB*NP, 3*HH, HH, 2,
                 r_in_b + l*3*HH, nullptr, p_qkvr, 0, p_part);
        attn_kernel<<<dim3(NB, NHEAD), 128>>>(p_qkvr, p_qkvr + HH, p_qkvr + 2*HH, p_o3,
                                              NP, NP,
                                              3*HH, (long long)NP*3*HH,
                                              3*HH, (long long)NP*3*HH,
                                              3*HH, (long long)NP*3*HH,
                                              HH,   (long long)NP*HH);
        run_gemm(p_o3, r_out_w + (size_t)l*HH*HH, NB*NP, HH, HH, 4,
                 r_out_b + l*HH, p_plan, p_plan, 0, p_part);
        ln_kernel<<<NB*NP, 256>>>(p_plan, r_ln2_g + l*HH, r_ln2_b + l*HH, p_y);
        run_gemm(p_y, r_w1 + (size_t)l*4*HH*HH, NB*NP, 4*HH, HH, 2,
                 r_b1 + l*4*HH, nullptr, p_ffn, 1, p_part);
        run_gemm(p_ffn, r_w2 + (size_t)l*HH*4*HH, NB*NP, HH, 4*HH, 8,
                 r_b2 + l*HH, p_plan, p_plan, 0, p_part);
    }

    // 6) outputs
    int ncopy = out_size < PLAN_ELEMS ? out_size : PLAN_ELEMS;
    copy_plan_kernel<<<(ncopy + 255) / 256, 256>>>(out, ncopy);
    red_kernel<<<16, 128>>>();
    finalize_kernel<<<1, 256>>>(out, out_size);
}

// round 2
// speedup vs baseline: 1.1534x; 1.1534x over previous
#include <cuda_runtime.h>
#include <math.h>

// ---------------- problem constants ----------------
#define NB 16      // batch
#define NT 4096    // tokens
#define HH 1024    // hidden
#define NS 16      // segments
#define NP 6       // plan slots
#define NHEAD 8
#define DHD 128    // head dim
#define PLAN_ELEMS (NB*NP*HH)   // 98304

// ---------------- device scratch (static, no allocs) ----------------
__device__ int   g_bounds[NB*(NS+1)];
__device__ float g_poolpart[4*NB*NS*HH];      // 1M floats
__device__ float g_seg0[NB*NS*HH];
__device__ float g_qkv[NB*NS*3*HH];
__device__ float g_o[NB*NS*HH];
__device__ float g_tmp[NB*NS*HH];
__device__ float g_seg1[NB*NS*HH];
__device__ float g_hbuf[NB*NS*HH];
__device__ float g_logits[NB*NS];
__device__ float g_sal[NB*NS];
__device__ float g_wseg[NB*NS*HH];
__device__ float g_qh[NP*HH];
__device__ float g_kv[NB*NS*2*HH];
__device__ float g_o2[NB*NP*HH];
__device__ float g_plan[NB*NP*HH];
__device__ float g_y[NB*NP*HH];
__device__ float g_qkvr[NB*NP*3*HH];
__device__ float g_o3[NB*NP*HH];
__device__ float g_ffn[NB*NP*4*HH];
__device__ float g_part[2*1024*1024];          // split-K partials
__device__ float g_entpart[NB];
__device__ float g_redpart[NB];

// ---------------- lengths + segment bounds ----------------
__global__ void lengths_kernel(const int* __restrict__ mask) {
    int b = blockIdx.x;
    __shared__ int red[256];
    int t = threadIdx.x;
    int s = 0;
    for (int i = t; i < NT; i += 256) s += mask[b*NT + i];
    red[t] = s; __syncthreads();
    for (int o = 128; o > 0; o >>= 1) { if (t < o) red[t] += red[t+o]; __syncthreads(); }
    if (t == 0) {
        int L = red[0];
        for (int k = 0; k <= NS; k++) g_bounds[b*(NS+1) + k] = (k * L) / NS;
    }
}

// ---------------- segment pooling (split over 4 row-slices) ----------------
__global__ void segpool_partial(const float* __restrict__ ts) {
    int seg = blockIdx.x;            // 0..255
    int b = seg >> 4, s = seg & 15;
    int slice = blockIdx.y;          // 0..3
    int lo = g_bounds[b*(NS+1) + s], hi = g_bounds[b*(NS+1) + s + 1];
    int cnt = hi - lo;
    int chunk = (cnt + 3) >> 2;
    int r0 = lo + slice * chunk;
    int r1 = min(hi, r0 + chunk);
    int t = threadIdx.x;             // 256 threads, 4 cols each
    float4 acc = make_float4(0.f,0.f,0.f,0.f);
    const float* base = ts + (size_t)b * NT * HH;
    for (int r = r0; r < r1; r++) {
        float4 v = *(const float4*)(base + (size_t)r * HH + t * 4);
        acc.x += v.x; acc.y += v.y; acc.z += v.z; acc.w += v.w;
    }
    *(float4*)&g_poolpart[((size_t)slice * NB*NS + seg) * HH + t * 4] = acc;
}

__global__ void segpool_finish() {
    int idx = blockIdx.x * 256 + threadIdx.x;   // < 262144
    int seg = idx >> 10;
    int b = seg >> 4, s = seg & 15;
    float cnt = (float)(g_bounds[b*(NS+1)+s+1] - g_bounds[b*(NS+1)+s]);
    const int ST = NB*NS*HH;
    float v = g_poolpart[idx] + g_poolpart[ST + idx] + g_poolpart[2*ST + idx] + g_poolpart[3*ST + idx];
    g_seg0[idx] = v / fmaxf(cnt, 1.f);
}

// ---------------- split-K GEMM: P[z] = A[M,K] @ W[N,K]^T, K-slice z ----------------
// 64x64 block tile, 128 threads, per-thread 8(M) x 4(N) register tile.
// Per k-step: 3x LDS.128 for 32 FMAs -> fma-pipe bound, not crossbar bound.
__global__ void __launch_bounds__(128) gemm_part_kernel(
    const float* __restrict__ A, const float* __restrict__ W,
    float* __restrict__ P, int M, int N, int K, int kslices)
{
    __shared__ float As[16][64];
    __shared__ float Ws[16][64];
    int m0 = blockIdx.x * 64;
    int n0 = blockIdx.y * 64;
    int Kper = K / kslices;
    int k0 = blockIdx.z * Kper;
    int tid = threadIdx.x;

    // loader indices: each thread loads 2 float4 of A-tile and 2 of W-tile
    int lr = tid >> 1;            // row within tile, 0..63
    int lk = (tid & 1) * 8;       // k offset 0 or 8

    // compute indices
    int tm = tid >> 4;            // 0..7   -> rows m0 + tm*8 .. +7
    int tn = tid & 15;            // 0..15  -> cols n0 + tn*4 .. +3

    float acc[8][4];
#pragma unroll
    for (int i = 0; i < 8; i++)
#pragma unroll
        for (int j = 0; j < 4; j++) acc[i][j] = 0.f;

    for (int kt = 0; kt < Kper; kt += 16) {
        int kb = k0 + kt;
        float4 va0 = make_float4(0.f,0.f,0.f,0.f), va1 = va0;
        int gm = m0 + lr;
        if (gm < M) {
            const float* ap = A + (size_t)gm * K + kb + lk;
            va0 = *(const float4*)(ap);
            va1 = *(const float4*)(ap + 4);
        }
        const float* wp = W + (size_t)(n0 + lr) * K + kb + lk;   // N always mult of 64
        float4 vw0 = *(const float4*)(wp);
        float4 vw1 = *(const float4*)(wp + 4);

        As[lk+0][lr] = va0.x; As[lk+1][lr] = va0.y; As[lk+2][lr] = va0.z; As[lk+3][lr] = va0.w;
        As[lk+4][lr] = va1.x; As[lk+5][lr] = va1.y; As[lk+6][lr] = va1.z; As[lk+7][lr] = va1.w;
        Ws[lk+0][lr] = vw0.x; Ws[lk+1][lr] = vw0.y; Ws[lk+2][lr] = vw0.z; Ws[lk+3][lr] = vw0.w;
        Ws[lk+4][lr] = vw1.x; Ws[lk+5][lr] = vw1.y; Ws[lk+6][lr] = vw1.z; Ws[lk+7][lr] = vw1.w;
        __syncthreads();
#pragma unroll
        for (int k = 0; k < 16; k++) {
            float a[8], b[4];
            *(float4*)&a[0] = *(const float4*)&As[k][tm*8];
            *(float4*)&a[4] = *(const float4*)&As[k][tm*8 + 4];
            *(float4*)&b[0] = *(const float4*)&Ws[k][tn*4];
#pragma unroll
            for (int i = 0; i < 8; i++)
#pragma unroll
                for (int j = 0; j < 4; j++) acc[i][j] = fmaf(a[i], b[j], acc[i][j]);
        }
        __syncthreads();
    }
    size_t base = (size_t)blockIdx.z * M * N;
#pragma unroll
    for (int i = 0; i < 8; i++) {
        int m = m0 + tm*8 + i;
        if (m >= M) continue;
        float4 v = make_float4(acc[i][0], acc[i][1], acc[i][2], acc[i][3]);
        *(float4*)(P + base + (size_t)m * N + n0 + tn*4) = v;
    }
}

// epilogue: out = [gelu]( sum_z P[z] + bias ) [+ res]
__global__ void epilogue_kernel(const float* __restrict__ P, const float* __restrict__ bias,
                                const float* __restrict__ res, float* __restrict__ out,
                                int M, int N, int kslices, int gelu)
{
    int idx = blockIdx.x * 256 + threadIdx.x;
    if (idx >= M * N) return;
    int n = idx % N;
    float v = 0.f;
    size_t MN = (size_t)M * N;
    for (int s = 0; s < kslices; s++) v += P[(size_t)s * MN + idx];
    v += bias[n];
    if (gelu) v = 0.5f * v * (1.f + erff(v * 0.70710678118654752f));
    if (res) v += res[idx];
    out[idx] = v;
}

// ---------------- generic small attention: one (b, head) per block ----------------
__global__ void attn_kernel(const float* __restrict__ qb, const float* __restrict__ kb,
                            const float* __restrict__ vb, float* __restrict__ ob,
                            int NQ, int NK,
                            int qRowStr, long long qBatStr,
                            int kRowStr, long long kBatStr,
                            int vRowStr, long long vBatStr,
                            int oRowStr, long long oBatStr)
{
    int b = blockIdx.x, h = blockIdx.y;
    const float* q = qb + b * qBatStr + h * DHD;
    const float* k = kb + b * kBatStr + h * DHD;
    const float* v = vb + b * vBatStr + h * DHD;
    float* o = ob + b * oBatStr + h * DHD;
    __shared__ float qs[16][DHD+1], ks[16][DHD+1], vs[16][DHD+1];
    __shared__ float pr[16][17];
    int t = threadIdx.x;  // 128
    for (int i = 0; i < NQ; i++) qs[i][t] = q[(size_t)i * qRowStr + t];
    for (int i = 0; i < NK; i++) { ks[i][t] = k[(size_t)i * kRowStr + t]; vs[i][t] = v[(size_t)i * vRowStr + t]; }
    __syncthreads();
    const float scale = 0.08838834764831843f;   // 1/sqrt(128)
    for (int p = t; p < NQ * NK; p += 128) {
        int qi = p / NK, ki = p - qi * NK;
        float acc = 0.f;
#pragma unroll 4
        for (int d = 0; d < DHD; d++) acc = fmaf(qs[qi][d], ks[ki][d], acc);
        pr[qi][ki] = acc * scale;
    }
    __syncthreads();
    if (t < NQ) {
        float mx = -1e30f;
        for (int kk = 0; kk < NK; kk++) mx = fmaxf(mx, pr[t][kk]);
        float sm = 0.f;
        for (int kk = 0; kk < NK; kk++) { float e = expf(pr[t][kk] - mx); pr[t][kk] = e; sm += e; }
        float inv = 1.f / sm;
        for (int kk = 0; kk < NK; kk++) pr[t][kk] *= inv;
    }
    __syncthreads();
    for (int j = t; j < NQ * DHD; j += 128) {
        int qi = j >> 7, d = j & 127;
        float acc = 0.f;
        for (int kk = 0; kk < NK; kk++) acc = fmaf(pr[qi][kk], vs[kk][d], acc);
        o[(size_t)qi * oRowStr + d] = acc;
    }
}

// ---------------- layernorm (two-pass, row per block) ----------------
__global__ void ln_kernel(const float* __restrict__ x,
                          const float* __restrict__ g, const float* __restrict__ be,
                          float* __restrict__ out)
{
    int r = blockIdx.x, t = threadIdx.x;   // 256 threads
    __shared__ float xs[HH];
    __shared__ float red[256];
    const float* xr = x + (size_t)r * HH;
    float s = 0.f;
    for (int i = t; i < HH; i += 256) { float v = xr[i]; xs[i] = v; s += v; }
    red[t] = s; __syncthreads();
    for (int o = 128; o > 0; o >>= 1) { if (t < o) red[t] += red[t+o]; __syncthreads(); }
    float mean = red[0] * (1.f / HH);
    __syncthreads();
    float s2 = 0.f;
    for (int i = t; i < HH; i += 256) { float d = xs[i] - mean; s2 += d * d; }
    red[t] = s2; __syncthreads();
    for (int o = 128; o > 0; o >>= 1) { if (t < o) red[t] += red[t+o]; __syncthreads(); }
    float inv = rsqrtf(red[0] * (1.f / HH) + 1e-5f);
    for (int i = t; i < HH; i += 256)
        out[(size_t)r * HH + i] = (xs[i] - mean) * inv * g[i] + be[i];
}

// ---------------- salience logits (dot with sal_w2) ----------------
__global__ void logits_kernel(const float* __restrict__ hbuf, const float* __restrict__ w,
                              const float* __restrict__ b2)
{
    int r = blockIdx.x, t = threadIdx.x;  // 128
    __shared__ float red[128];
    float s = 0.f;
    for (int i = t; i < HH; i += 128) s = fmaf(hbuf[(size_t)r * HH + i], w[i], s);
    red[t] = s; __syncthreads();
    for (int o = 64; o > 0; o >>= 1) { if (t < o) red[t] += red[t+o]; __syncthreads(); }
    if (t == 0) g_logits[r] = red[0] + b2[0];
}

// ---------------- salience softmax + entropy + weighted segments ----------------
__global__ void salience_kernel() {
    int b = blockIdx.x, t = threadIdx.x;  // 256
    __shared__ float sal_s[NS];
    if (t == 0) {
        float mx = -1e30f;
        for (int s = 0; s < NS; s++) mx = fmaxf(mx, g_logits[b*NS + s]);
        float sm = 0.f;
        for (int s = 0; s < NS; s++) { float e = expf(g_logits[b*NS + s] - mx); sal_s[s] = e; sm += e; }
        float inv = 1.f / sm, ent = 0.f;
        for (int s = 0; s < NS; s++) {
            sal_s[s] *= inv;
            g_sal[b*NS + s] = sal_s[s];
            ent -= sal_s[s] * logf(sal_s[s] + 1e-8f);
        }
        g_entpart[b] = ent;
    }
    __syncthreads();
    for (int i = t; i < NS * HH; i += 256) {
        int s = i >> 10;
        g_wseg[(size_t)b * NS * HH + i] = g_seg1[(size_t)b * NS * HH + i] * sal_s[s];
    }
}

// ---------------- redundancy ----------------
__global__ void red_kernel() {
    int b = blockIdx.x, t = threadIdx.x;  // 128
    __shared__ float ps[NP][HH+1];
    __shared__ float nrm[NP];
    __shared__ float parr[16];
    for (int i = t; i < NP * HH; i += 128) ps[i >> 10][i & 1023] = g_plan[(size_t)b * NP * HH + i];
    __syncthreads();
    if (t < NP) {
        float s = 0.f;
        for (int d = 0; d < HH; d++) s = fmaf(ps[t][d], ps[t][d], s);
        nrm[t] = fmaxf(sqrtf(s), 1e-12f);
    }
    __syncthreads();
    if (t < 15) {
        int i = 0, j = 0, c = t;
        for (i = 0; i < NP; i++) { int row = NP - 1 - i; if (c < row) { j = i + 1 + c; break; } c -= row; }
        float s = 0.f;
        for (int d = 0; d < HH; d++) s = fmaf(ps[i][d], ps[j][d], s);
        float sim = s / (nrm[i] * nrm[j]);
        parr[t] = 2.f * sim * sim;
    }
    __syncthreads();
    if (t == 0) {
        float s = 0.f;
        for (int p = 0; p < 15; p++) s += parr[p];
        g_redpart[b] = s;
    }
}

// ---------------- output assembly ----------------
__global__ void copy_plan_kernel(float* __restrict__ out, int n) {
    int i = blockIdx.x * 256 + threadIdx.x;
    if (i < n) out[i] = g_plan[i];
}

__global__ void finalize_kernel(float* __restrict__ out, int out_size) {
    int t = threadIdx.x;  // 256
    if (PLAN_ELEMS + t < out_size && t < NB*NS) out[PLAN_ELEMS + t] = g_sal[t];
    if (t == 0) {
        if (PLAN_ELEMS + 256 < out_size) {
            float e = 0.f;
            for (int b = 0; b < NB; b++) e += g_entpart[b];
            out[PLAN_ELEMS + 256] = e / (float)NB;
        }
        if (PLAN_ELEMS + 257 < out_size) {
            float r = 0.f;
            for (int b = 0; b < NB; b++) r += g_redpart[b];
            out[PLAN_ELEMS + 257] = r / (float)(NB * NP * (NP - 1));
        }
    }
}

// ---------------- host helper ----------------
static void run_gemm(const float* A, const float* W, int M, int N, int K, int ks,
                     const float* bias, const float* res, float* out, int gelu, float* part)
{
    dim3 grid((M + 63) / 64, (N + 63) / 64, ks);
    gemm_part_kernel<<<grid, 128>>>(A, W, part, M, N, K, ks);
    int tot = M * N;
    epilogue_kernel<<<(tot + 255) / 256, 256>>>(part, bias, res, out, M, N, ks, gelu);
}

extern "C" void kernel_launch(void* const* d_in, const int* in_sizes, int n_in,
                              void* d_out, int out_size)
{
    const float* ts       = (const float*)d_in[0];
    const int*   mask     = (const int*)  d_in[1];
    const float* sa_in_w  = (const float*)d_in[2];
    const float* sa_in_b  = (const float*)d_in[3];
    const float* sa_out_w = (const float*)d_in[4];
    const float* sa_out_b = (const float*)d_in[5];
    const float* ln_g     = (const float*)d_in[6];
    const float* ln_b     = (const float*)d_in[7];
    const float* sal_w1   = (const float*)d_in[8];
    const float* sal_b1   = (const float*)d_in[9];
    const float* sal_w2   = (const float*)d_in[10];
    const float* sal_b2   = (const float*)d_in[11];
    const float* plan_q   = (const float*)d_in[12];
    const float* qa_in_w  = (const float*)d_in[13];
    const float* qa_in_b  = (const float*)d_in[14];
    const float* qa_out_w = (const float*)d_in[15];
    const float* qa_out_b = (const float*)d_in[16];
    const float* r_in_w   = (const float*)d_in[17];
    const float* r_in_b   = (const float*)d_in[18];
    const float* r_out_w  = (const float*)d_in[19];
    const float* r_out_b  = (const float*)d_in[20];
    const float* r_ln1_g  = (const float*)d_in[21];
    const float* r_ln1_b  = (const float*)d_in[22];
    const float* r_ln2_g  = (const float*)d_in[23];
    const float* r_ln2_b  = (const float*)d_in[24];
    const float* r_w1     = (const float*)d_in[25];
    const float* r_b1     = (const float*)d_in[26];
    const float* r_w2     = (const float*)d_in[27];
    const float* r_b2     = (const float*)d_in[28];
    float* out = (float*)d_out;

    float *p_part, *p_seg0, *p_qkv, *p_o, *p_tmp, *p_seg1, *p_h, *p_qh, *p_kv,
          *p_o2, *p_plan, *p_y, *p_qkvr, *p_o3, *p_ffn, *p_wseg;
    cudaGetSymbolAddress((void**)&p_part, g_part);
    cudaGetSymbolAddress((void**)&p_seg0, g_seg0);
    cudaGetSymbolAddress((void**)&p_qkv,  g_qkv);
    cudaGetSymbolAddress((void**)&p_o,    g_o);
    cudaGetSymbolAddress((void**)&p_tmp,  g_tmp);
    cudaGetSymbolAddress((void**)&p_seg1, g_seg1);
    cudaGetSymbolAddress((void**)&p_h,    g_hbuf);
    cudaGetSymbolAddress((void**)&p_qh,   g_qh);
    cudaGetSymbolAddress((void**)&p_kv,   g_kv);
    cudaGetSymbolAddress((void**)&p_o2,   g_o2);
    cudaGetSymbolAddress((void**)&p_plan, g_plan);
    cudaGetSymbolAddress((void**)&p_y,    g_y);
    cudaGetSymbolAddress((void**)&p_qkvr, g_qkvr);
    cudaGetSymbolAddress((void**)&p_o3,   g_o3);
    cudaGetSymbolAddress((void**)&p_ffn,  g_ffn);
    cudaGetSymbolAddress((void**)&p_wseg, g_wseg);

    // 1) lengths + bounds, segment pooling
    lengths_kernel<<<16, 256>>>(mask);
    segpool_partial<<<dim3(NB*NS, 4), 256>>>(ts);
    segpool_finish<<<(NB*NS*HH)/256, 256>>>();

    // 2) segment self-attention
    run_gemm(p_seg0, sa_in_w, 256, 3*HH, HH, 2, sa_in_b, nullptr, p_qkv, 0, p_part);   // 384 blocks
    attn_kernel<<<dim3(NB, NHEAD), 128>>>(p_qkv, p_qkv + HH, p_qkv + 2*HH, p_o,
                                          16, 16,
                                          3*HH, (long long)NS*3*HH,
                                          3*HH, (long long)NS*3*HH,
                                          3*HH, (long long)NS*3*HH,
                                          HH,   (long long)NS*HH);
    run_gemm(p_o, sa_out_w, 256, HH, HH, 4, sa_out_b, p_seg0, p_tmp, 0, p_part);       // 256 blocks
    ln_kernel<<<256, 256>>>(p_tmp, ln_g, ln_b, p_seg1);

    // 3) salience
    run_gemm(p_seg1, sal_w1, 256, HH, HH, 4, sal_b1, nullptr, p_h, 1, p_part);         // 256 blocks
    logits_kernel<<<256, 128>>>(p_h, sal_w2, sal_b2);
    salience_kernel<<<16, 256>>>();

    // 4) plan cross-attention (qh is batch-independent)
    run_gemm(plan_q, qa_in_w, NP, HH, HH, 8, qa_in_b, nullptr, p_qh, 0, p_part);       // 128 blocks
    run_gemm(p_wseg, qa_in_w + (size_t)HH*HH, 256, 2*HH, HH, 2, qa_in_b + HH, nullptr, p_kv, 0, p_part); // 256
    attn_kernel<<<dim3(NB, NHEAD), 128>>>(p_qh, p_kv, p_kv + HH, p_o2,
                                          NP, 16,
                                          HH,   0LL,
                                          2*HH, (long long)NS*2*HH,
                                          2*HH, (long long)NS*2*HH,
                                          HH,   (long long)NP*HH);
    run_gemm(p_o2, qa_out_w, NB*NP, HH, HH, 8, qa_out_b, nullptr, p_plan, 0, p_part);  // 256 blocks

    // 5) refinement transformer layers (norm_first)
    for (int l = 0; l < 2; l++) {
        ln_kernel<<<NB*NP, 256>>>(p_plan, r_ln1_g + l*HH, r_ln1_b + l*HH, p_y);
        run_gemm(p_y, r_in_w + (size_t)l*3*HH*HH, NB*NP, 3*HH, HH, 4,
                 r_in_b + l*3*HH, nullptr, p_qkvr, 0, p_part);                          // 384 blocks
        attn_kernel<<<dim3(NB, NHEAD), 128>>>(p_qkvr, p_qkvr + HH, p_qkvr + 2*HH, p_o3,
                                              NP, NP,
                                              3*HH, (long long)NP*3*HH,
                                              3*HH, (long long)NP*3*HH,
                                              3*HH, (long long)NP*3*HH,
                                              HH,   (long long)NP*HH);
        run_gemm(p_o3, r_out_w + (size_t)l*HH*HH, NB*NP, HH, HH, 8,
                 r_out_b + l*HH, p_plan, p_plan, 0, p_part);                            // 256 blocks
        ln_kernel<<<NB*NP, 256>>>(p_plan, r_ln2_g + l*HH, r_ln2_b + l*HH, p_y);
        run_gemm(p_y, r_w1 + (size_t)l*4*HH*HH, NB*NP, 4*HH, HH, 2,
                 r_b1 + l*4*HH, nullptr, p_ffn, 1, p_part);                             // 256 blocks
        run_gemm(p_ffn, r_w2 + (size_t)l*HH*4*HH, NB*NP, HH, 4*HH, 8,
                 r_b2 + l*HH, p_plan, p_plan, 0, p_part);                               // 256 blocks
    }

    // 6) outputs
    int ncopy = out_size < PLAN_ELEMS ? out_size : PLAN_ELEMS;
    copy_plan_kernel<<<(ncopy + 255) / 256, 256>>>(out, ncopy);
    red_kernel<<<16, 128>>>();
    finalize_kernel<<<1, 256>>>(out, out_size);
}

// round 3
// speedup vs baseline: 1.3345x; 1.1570x over previous
#include <cuda_runtime.h>
#include <math.h>

// ---------------- problem constants ----------------
#define NB 16      // batch
#define NT 4096    // tokens
#define HH 1024    // hidden
#define NS 16      // segments
#define NP 6       // plan slots
#define NHEAD 8
#define DHD 128    // head dim
#define PLAN_ELEMS (NB*NP*HH)   // 98304

// ---------------- device scratch (static, no allocs) ----------------
__device__ int   g_bounds[NB*(NS+1)];
__device__ float g_poolpart[4*NB*NS*HH];
__device__ float g_seg0[NB*NS*HH];
__device__ float g_qkv[NB*NS*3*HH];
__device__ float g_o[NB*NS*HH];
__device__ float g_tmp[NB*NS*HH];
__device__ float g_seg1[NB*NS*HH];
__device__ float g_hbuf[NB*NS*HH];
__device__ float g_logits[NB*NS];
__device__ float g_sal[NB*NS];
__device__ float g_wseg[NB*NS*HH];
__device__ float g_qh[64*HH];
__device__ float g_kv[NB*NS*2*HH];
__device__ float g_o2[NB*NP*HH];
__device__ float g_plan[NB*NP*HH];
__device__ float g_y[NB*NP*HH];
__device__ float g_qkvr[NB*NP*3*HH];
__device__ float g_o3[NB*NP*HH];
__device__ float g_ffn[NB*NP*4*HH];
__device__ float g_part[4*1024*1024];          // split-K partials (16MB)
__device__ float g_entpart[NB];
__device__ float g_redpart[NB];

// ---------------- lengths + segment bounds ----------------
__global__ void lengths_kernel(const int* __restrict__ mask) {
    int b = blockIdx.x;
    __shared__ int red[256];
    int t = threadIdx.x;
    int s = 0;
    for (int i = t; i < NT; i += 256) s += mask[b*NT + i];
    red[t] = s; __syncthreads();
    for (int o = 128; o > 0; o >>= 1) { if (t < o) red[t] += red[t+o]; __syncthreads(); }
    if (t == 0) {
        int L = red[0];
        for (int k = 0; k <= NS; k++) g_bounds[b*(NS+1) + k] = (k * L) / NS;
    }
}

// ---------------- segment pooling (split over 4 row-slices) ----------------
__global__ void segpool_partial(const float* __restrict__ ts) {
    int seg = blockIdx.x;            // 0..255
    int b = seg >> 4, s = seg & 15;
    int slice = blockIdx.y;          // 0..3
    int lo = g_bounds[b*(NS+1) + s], hi = g_bounds[b*(NS+1) + s + 1];
    int cnt = hi - lo;
    int chunk = (cnt + 3) >> 2;
    int r0 = lo + slice * chunk;
    int r1 = min(hi, r0 + chunk);
    int t = threadIdx.x;             // 256 threads, 4 cols each
    float4 acc = make_float4(0.f,0.f,0.f,0.f);
    const float* base = ts + (size_t)b * NT * HH;
    for (int r = r0; r < r1; r++) {
        float4 v = *(const float4*)(base + (size_t)r * HH + t * 4);
        acc.x += v.x; acc.y += v.y; acc.z += v.z; acc.w += v.w;
    }
    *(float4*)&g_poolpart[((size_t)slice * NB*NS + seg) * HH + t * 4] = acc;
}

__global__ void segpool_finish() {
    int idx = blockIdx.x * 256 + threadIdx.x;   // < 262144
    int seg = idx >> 10;
    int b = seg >> 4, s = seg & 15;
    float cnt = (float)(g_bounds[b*(NS+1)+s+1] - g_bounds[b*(NS+1)+s]);
    const int ST = NB*NS*HH;
    float v = g_poolpart[idx] + g_poolpart[ST + idx] + g_poolpart[2*ST + idx] + g_poolpart[3*ST + idx];
    g_seg0[idx] = v / fmaxf(cnt, 1.f);
}

// ---------------- split-K GEMM: P[z] = A[M,K] @ W[N,K]^T, K-slice z ----------------
// 64(M) x 128(N) block tile, BK=16, 128 threads, per-thread 8x8 via fma.rn.f32x2.
#define BM 64
#define BN 128
#define BK 16

__global__ void __launch_bounds__(128) gemm_part_kernel(
    const float* __restrict__ A, const float* __restrict__ W,
    float* __restrict__ P, int M, int N, int K, int kslices)
{
    __shared__ float As[BK][68];    // [k][m], padded
    __shared__ float Ws[BK][132];   // [k][n], padded
    int m0 = blockIdx.x * BM;
    int n0 = blockIdx.y * BN;
    int Kper = K / kslices;
    int k0 = blockIdx.z * Kper;
    int tid = threadIdx.x;

    int tm = tid >> 4;        // 0..7 -> rows m0+tm*8..+7
    int tn = tid & 15;        // 0..15 -> cols n0+tn*8..+7

    unsigned long long acc[4][8];   // packed pairs along M: lo=row 2mp, hi=row 2mp+1
#pragma unroll
    for (int i = 0; i < 4; i++)
#pragma unroll
        for (int j = 0; j < 8; j++) acc[i][j] = 0ULL;

    float4 va[2], vw[4];
    // initial tile load
    {
#pragma unroll
        for (int i = 0; i < 2; i++) {
            int f = tid + i*128; int row = f >> 2, kg = f & 3;
            va[i] = (m0 + row < M) ? *(const float4*)(A + (size_t)(m0+row)*K + k0 + kg*4)
                                   : make_float4(0.f,0.f,0.f,0.f);
        }
#pragma unroll
        for (int i = 0; i < 4; i++) {
            int f = tid + i*128; int row = f >> 2, kg = f & 3;
            vw[i] = *(const float4*)(W + (size_t)(n0+row)*K + k0 + kg*4);
        }
    }

    int ntiles = Kper / BK;
    for (int t = 0; t < ntiles; t++) {
        // STS (transpose)
#pragma unroll
        for (int i = 0; i < 2; i++) {
            int f = tid + i*128; int row = f >> 2, kg = f & 3;
            As[kg*4+0][row] = va[i].x; As[kg*4+1][row] = va[i].y;
            As[kg*4+2][row] = va[i].z; As[kg*4+3][row] = va[i].w;
        }
#pragma unroll
        for (int i = 0; i < 4; i++) {
            int f = tid + i*128; int row = f >> 2, kg = f & 3;
            Ws[kg*4+0][row] = vw[i].x; Ws[kg*4+1][row] = vw[i].y;
            Ws[kg*4+2][row] = vw[i].z; Ws[kg*4+3][row] = vw[i].w;
        }
        __syncthreads();
        // prefetch next tile into regs (overlaps with compute below)
        if (t + 1 < ntiles) {
            int kb = k0 + (t+1)*BK;
#pragma unroll
            for (int i = 0; i < 2; i++) {
                int f = tid + i*128; int row = f >> 2, kg = f & 3;
                va[i] = (m0 + row < M) ? *(const float4*)(A + (size_t)(m0+row)*K + kb + kg*4)
                                       : make_float4(0.f,0.f,0.f,0.f);
            }
#pragma unroll
            for (int i = 0; i < 4; i++) {
                int f = tid + i*128; int row = f >> 2, kg = f & 3;
                vw[i] = *(const float4*)(W + (size_t)(n0+row)*K + kb + kg*4);
            }
        }
#pragma unroll
        for (int k = 0; k < BK; k++) {
            unsigned long long a64[4];
#pragma unroll
            for (int mp = 0; mp < 4; mp++)
                a64[mp] = *(const unsigned long long*)&As[k][tm*8 + 2*mp];
            float4 b0 = *(const float4*)&Ws[k][tn*8];
            float4 b1 = *(const float4*)&Ws[k][tn*8 + 4];
            float bv[8] = {b0.x,b0.y,b0.z,b0.w,b1.x,b1.y,b1.z,b1.w};
#pragma unroll
            for (int n = 0; n < 8; n++) {
                unsigned long long bd;
                unsigned bi = __float_as_uint(bv[n]);
                asm("mov.b64 %0, {%1, %1};" : "=l"(bd) : "r"(bi));
#pragma unroll
                for (int mp = 0; mp < 4; mp++)
                    asm("fma.rn.f32x2 %0, %1, %2, %0;"
                        : "+l"(acc[mp][n]) : "l"(a64[mp]), "l"(bd));
            }
        }
        __syncthreads();
    }

    size_t base = (size_t)blockIdx.z * M * N;
#pragma unroll
    for (int mp = 0; mp < 4; mp++) {
#pragma unroll
        for (int half = 0; half < 2; half++) {
            int m = m0 + tm*8 + 2*mp + half;
            if (m >= M) continue;
            float f[8];
#pragma unroll
            for (int n = 0; n < 8; n++) {
                float lo, hi;
                asm("mov.b64 {%0, %1}, %2;" : "=f"(lo), "=f"(hi) : "l"(acc[mp][n]));
                f[n] = half ? hi : lo;
            }
            float* op = P + base + (size_t)m * N + n0 + tn*8;
            *(float4*)op       = make_float4(f[0],f[1],f[2],f[3]);
            *(float4*)(op + 4) = make_float4(f[4],f[5],f[6],f[7]);
        }
    }
}

// epilogue: out = [gelu]( sum_z P[z] + bias ) [+ res]
__global__ void epilogue_kernel(const float* __restrict__ P, const float* __restrict__ bias,
                                const float* __restrict__ res, float* __restrict__ out,
                                int M, int N, int kslices, int gelu)
{
    int idx = blockIdx.x * 256 + threadIdx.x;
    if (idx >= M * N) return;
    int n = idx % N;
    float v = 0.f;
    size_t MN = (size_t)M * N;
    for (int s = 0; s < kslices; s++) v += P[(size_t)s * MN + idx];
    v += bias[n];
    if (gelu) v = 0.5f * v * (1.f + erff(v * 0.70710678118654752f));
    if (res) v += res[idx];
    out[idx] = v;
}

// ---------------- generic small attention: one (b, head) per block ----------------
__global__ void attn_kernel(const float* __restrict__ qb, const float* __restrict__ kb,
                            const float* __restrict__ vb, float* __restrict__ ob,
                            int NQ, int NK,
                            int qRowStr, long long qBatStr,
                            int kRowStr, long long kBatStr,
                            int vRowStr, long long vBatStr,
                            int oRowStr, long long oBatStr)
{
    int b = blockIdx.x, h = blockIdx.y;
    const float* q = qb + b * qBatStr + h * DHD;
    const float* k = kb + b * kBatStr + h * DHD;
    const float* v = vb + b * vBatStr + h * DHD;
    float* o = ob + b * oBatStr + h * DHD;
    __shared__ float qs[16][DHD+1], ks[16][DHD+1], vs[16][DHD+1];
    __shared__ float pr[16][17];
    int t = threadIdx.x;  // 128
    for (int i = 0; i < NQ; i++) qs[i][t] = q[(size_t)i * qRowStr + t];
    for (int i = 0; i < NK; i++) { ks[i][t] = k[(size_t)i * kRowStr + t]; vs[i][t] = v[(size_t)i * vRowStr + t]; }
    __syncthreads();
    const float scale = 0.08838834764831843f;   // 1/sqrt(128)
    for (int p = t; p < NQ * NK; p += 128) {
        int qi = p / NK, ki = p - qi * NK;
        float acc = 0.f;
#pragma unroll 4
        for (int d = 0; d < DHD; d++) acc = fmaf(qs[qi][d], ks[ki][d], acc);
        pr[qi][ki] = acc * scale;
    }
    __syncthreads();
    if (t < NQ) {
        float mx = -1e30f;
        for (int kk = 0; kk < NK; kk++) mx = fmaxf(mx, pr[t][kk]);
        float sm = 0.f;
        for (int kk = 0; kk < NK; kk++) { float e = expf(pr[t][kk] - mx); pr[t][kk] = e; sm += e; }
        float inv = 1.f / sm;
        for (int kk = 0; kk < NK; kk++) pr[t][kk] *= inv;
    }
    __syncthreads();
    for (int j = t; j < NQ * DHD; j += 128) {
        int qi = j >> 7, d = j & 127;
        float acc = 0.f;
        for (int kk = 0; kk < NK; kk++) acc = fmaf(pr[qi][kk], vs[kk][d], acc);
        o[(size_t)qi * oRowStr + d] = acc;
    }
}

// ---------------- layernorm (two-pass, row per block) ----------------
__global__ void ln_kernel(const float* __restrict__ x,
                          const float* __restrict__ g, const float* __restrict__ be,
                          float* __restrict__ out)
{
    int r = blockIdx.x, t = threadIdx.x;   // 256 threads
    __shared__ float xs[HH];
    __shared__ float red[256];
    const float* xr = x + (size_t)r * HH;
    float s = 0.f;
    for (int i = t; i < HH; i += 256) { float v = xr[i]; xs[i] = v; s += v; }
    red[t] = s; __syncthreads();
    for (int o = 128; o > 0; o >>= 1) { if (t < o) red[t] += red[t+o]; __syncthreads(); }
    float mean = red[0] * (1.f / HH);
    __syncthreads();
    float s2 = 0.f;
    for (int i = t; i < HH; i += 256) { float d = xs[i] - mean; s2 += d * d; }
    red[t] = s2; __syncthreads();
    for (int o = 128; o > 0; o >>= 1) { if (t < o) red[t] += red[t+o]; __syncthreads(); }
    float inv = rsqrtf(red[0] * (1.f / HH) + 1e-5f);
    for (int i = t; i < HH; i += 256)
        out[(size_t)r * HH + i] = (xs[i] - mean) * inv * g[i] + be[i];
}

// ---------------- salience logits (dot with sal_w2) ----------------
__global__ void logits_kernel(const float* __restrict__ hbuf, const float* __restrict__ w,
                              const float* __restrict__ b2)
{
    int r = blockIdx.x, t = threadIdx.x;  // 128
    __shared__ float red[128];
    float s = 0.f;
    for (int i = t; i < HH; i += 128) s = fmaf(hbuf[(size_t)r * HH + i], w[i], s);
    red[t] = s; __syncthreads();
    for (int o = 64; o > 0; o >>= 1) { if (t < o) red[t] += red[t+o]; __syncthreads(); }
    if (t == 0) g_logits[r] = red[0] + b2[0];
}

// ---------------- salience softmax + entropy + weighted segments ----------------
__global__ void salience_kernel() {
    int b = blockIdx.x, t = threadIdx.x;  // 256
    __shared__ float sal_s[NS];
    if (t == 0) {
        float mx = -1e30f;
        for (int s = 0; s < NS; s++) mx = fmaxf(mx, g_logits[b*NS + s]);
        float sm = 0.f;
        for (int s = 0; s < NS; s++) { float e = expf(g_logits[b*NS + s] - mx); sal_s[s] = e; sm += e; }
        float inv = 1.f / sm, ent = 0.f;
        for (int s = 0; s < NS; s++) {
            sal_s[s] *= inv;
            g_sal[b*NS + s] = sal_s[s];
            ent -= sal_s[s] * logf(sal_s[s] + 1e-8f);
        }
        g_entpart[b] = ent;
    }
    __syncthreads();
    for (int i = t; i < NS * HH; i += 256) {
        int s = i >> 10;
        g_wseg[(size_t)b * NS * HH + i] = g_seg1[(size_t)b * NS * HH + i] * sal_s[s];
    }
}

// ---------------- redundancy ----------------
__global__ void red_kernel() {
    int b = blockIdx.x, t = threadIdx.x;  // 128
    __shared__ float ps[NP][HH+1];
    __shared__ float nrm[NP];
    __shared__ float parr[16];
    for (int i = t; i < NP * HH; i += 128) ps[i >> 10][i & 1023] = g_plan[(size_t)b * NP * HH + i];
    __syncthreads();
    if (t < NP) {
        float s = 0.f;
        for (int d = 0; d < HH; d++) s = fmaf(ps[t][d], ps[t][d], s);
        nrm[t] = fmaxf(sqrtf(s), 1e-12f);
    }
    __syncthreads();
    if (t < 15) {
        int i = 0, j = 0, c = t;
        for (i = 0; i < NP; i++) { int row = NP - 1 - i; if (c < row) { j = i + 1 + c; break; } c -= row; }
        float s = 0.f;
        for (int d = 0; d < HH; d++) s = fmaf(ps[i][d], ps[j][d], s);
        float sim = s / (nrm[i] * nrm[j]);
        parr[t] = 2.f * sim * sim;
    }
    __syncthreads();
    if (t == 0) {
        float s = 0.f;
        for (int p = 0; p < 15; p++) s += parr[p];
        g_redpart[b] = s;
    }
}

// ---------------- output assembly ----------------
__global__ void copy_plan_kernel(float* __restrict__ out, int n) {
    int i = blockIdx.x * 256 + threadIdx.x;
    if (i < n) out[i] = g_plan[i];
}

__global__ void finalize_kernel(float* __restrict__ out, int out_size) {
    int t = threadIdx.x;  // 256
    if (PLAN_ELEMS + t < out_size && t < NB*NS) out[PLAN_ELEMS + t] = g_sal[t];
    if (t == 0) {
        if (PLAN_ELEMS + 256 < out_size) {
            float e = 0.f;
            for (int b = 0; b < NB; b++) e += g_entpart[b];
            out[PLAN_ELEMS + 256] = e / (float)NB;
        }
        if (PLAN_ELEMS + 257 < out_size) {
            float r = 0.f;
            for (int b = 0; b < NB; b++) r += g_redpart[b];
            out[PLAN_ELEMS + 257] = r / (float)(NB * NP * (NP - 1));
        }
    }
}

// ---------------- host helper ----------------
static void run_gemm(const float* A, const float* W, int M, int N, int K, int ks,
                     const float* bias, const float* res, float* out, int gelu, float* part)
{
    dim3 grid((M + BM - 1) / BM, (N + BN - 1) / BN, ks);
    gemm_part_kernel<<<grid, 128>>>(A, W, part, M, N, K, ks);
    int tot = M * N;
    epilogue_kernel<<<(tot + 255) / 256, 256>>>(part, bias, res, out, M, N, ks, gelu);
}

extern "C" void kernel_launch(void* const* d_in, const int* in_sizes, int n_in,
                              void* d_out, int out_size)
{
    const float* ts       = (const float*)d_in[0];
    const int*   mask     = (const int*)  d_in[1];
    const float* sa_in_w  = (const float*)d_in[2];
    const float* sa_in_b  = (const float*)d_in[3];
    const float* sa_out_w = (const float*)d_in[4];
    const float* sa_out_b = (const float*)d_in[5];
    const float* ln_g     = (const float*)d_in[6];
    const float* ln_b     = (const float*)d_in[7];
    const float* sal_w1   = (const float*)d_in[8];
    const float* sal_b1   = (const float*)d_in[9];
    const float* sal_w2   = (const float*)d_in[10];
    const float* sal_b2   = (const float*)d_in[11];
    const float* plan_q   = (const float*)d_in[12];
    const float* qa_in_w  = (const float*)d_in[13];
    const float* qa_in_b  = (const float*)d_in[14];
    const float* qa_out_w = (const float*)d_in[15];
    const float* qa_out_b = (const float*)d_in[16];
    const float* r_in_w   = (const float*)d_in[17];
    const float* r_in_b   = (const float*)d_in[18];
    const float* r_out_w  = (const float*)d_in[19];
    const float* r_out_b  = (const float*)d_in[20];
    const float* r_ln1_g  = (const float*)d_in[21];
    const float* r_ln1_b  = (const float*)d_in[22];
    const float* r_ln2_g  = (const float*)d_in[23];
    const float* r_ln2_b  = (const float*)d_in[24];
    const float* r_w1     = (const float*)d_in[25];
    const float* r_b1     = (const float*)d_in[26];
    const float* r_w2     = (const float*)d_in[27];
    const float* r_b2     = (const float*)d_in[28];
    float* out = (float*)d_out;

    float *p_part, *p_seg0, *p_qkv, *p_o, *p_tmp, *p_seg1, *p_h, *p_qh, *p_kv,
          *p_o2, *p_plan, *p_y, *p_qkvr, *p_o3, *p_ffn, *p_wseg;
    cudaGetSymbolAddress((void**)&p_part, g_part);
    cudaGetSymbolAddress((void**)&p_seg0, g_seg0);
    cudaGetSymbolAddress((void**)&p_qkv,  g_qkv);
    cudaGetSymbolAddress((void**)&p_o,    g_o);
    cudaGetSymbolAddress((void**)&p_tmp,  g_tmp);
    cudaGetSymbolAddress((void**)&p_seg1, g_seg1);
    cudaGetSymbolAddress((void**)&p_h,    g_hbuf);
    cudaGetSymbolAddress((void**)&p_qh,   g_qh);
    cudaGetSymbolAddress((void**)&p_kv,   g_kv);
    cudaGetSymbolAddress((void**)&p_o2,   g_o2);
    cudaGetSymbolAddress((void**)&p_plan, g_plan);
    cudaGetSymbolAddress((void**)&p_y,    g_y);
    cudaGetSymbolAddress((void**)&p_qkvr, g_qkvr);
    cudaGetSymbolAddress((void**)&p_o3,   g_o3);
    cudaGetSymbolAddress((void**)&p_ffn,  g_ffn);
    cudaGetSymbolAddress((void**)&p_wseg, g_wseg);

    // 1) lengths + bounds, segment pooling
    lengths_kernel<<<16, 256>>>(mask);
    segpool_partial<<<dim3(NB*NS, 4), 256>>>(ts);
    segpool_finish<<<(NB*NS*HH)/256, 256>>>();

    // 2) segment self-attention
    run_gemm(p_seg0, sa_in_w, 256, 3*HH, HH, 4, sa_in_b, nullptr, p_qkv, 0, p_part);   // 384 blocks
    attn_kernel<<<dim3(NB, NHEAD), 128>>>(p_qkv, p_qkv + HH, p_qkv + 2*HH, p_o,
                                          16, 16,
                                          3*HH, (long long)NS*3*HH,
                                          3*HH, (long long)NS*3*HH,
                                          3*HH, (long long)NS*3*HH,
                                          HH,   (long long)NS*HH);
    run_gemm(p_o, sa_out_w, 256, HH, HH, 8, sa_out_b, p_seg0, p_tmp, 0, p_part);       // 256 blocks
    ln_kernel<<<256, 256>>>(p_tmp, ln_g, ln_b, p_seg1);

    // 3) salience
    run_gemm(p_seg1, sal_w1, 256, HH, HH, 8, sal_b1, nullptr, p_h, 1, p_part);         // 256 blocks
    logits_kernel<<<256, 128>>>(p_h, sal_w2, sal_b2);
    salience_kernel<<<16, 256>>>();

    // 4) plan cross-attention (qh is batch-independent)
    run_gemm(plan_q, qa_in_w, NP, HH, HH, 8, qa_in_b, nullptr, p_qh, 0, p_part);       // 64 blocks
    run_gemm(p_wseg, qa_in_w + (size_t)HH*HH, 256, 2*HH, HH, 4, qa_in_b + HH, nullptr, p_kv, 0, p_part); // 256
    attn_kernel<<<dim3(NB, NHEAD), 128>>>(p_qh, p_kv, p_kv + HH, p_o2,
                                          NP, 16,
                                          HH,   0LL,
                                          2*HH, (long long)NS*2*HH,
                                          2*HH, (long long)NS*2*HH,
                                          HH,   (long long)NP*HH);
    run_gemm(p_o2, qa_out_w, NB*NP, HH, HH, 16, qa_out_b, nullptr, p_plan, 0, p_part); // 256 blocks

    // 5) refinement transformer layers (norm_first)
    for (int l = 0; l < 2; l++) {
        ln_kernel<<<NB*NP, 256>>>(p_plan, r_ln1_g + l*HH, r_ln1_b + l*HH, p_y);
        run_gemm(p_y, r_in_w + (size_t)l*3*HH*HH, NB*NP, 3*HH, HH, 8,
                 r_in_b + l*3*HH, nullptr, p_qkvr, 0, p_part);                          // 384 blocks
        attn_kernel<<<dim3(NB, NHEAD), 128>>>(p_qkvr, p_qkvr + HH, p_qkvr + 2*HH, p_o3,
                                              NP, NP,
                                              3*HH, (long long)NP*3*HH,
                                              3*HH, (long long)NP*3*HH,
                                              3*HH, (long long)NP*3*HH,
                                              HH,   (long long)NP*HH);
        run_gemm(p_o3, r_out_w + (size_t)l*HH*HH, NB*NP, HH, HH, 16,
                 r_out_b + l*HH, p_plan, p_plan, 0, p_part);                            // 256 blocks
        ln_kernel<<<NB*NP, 256>>>(p_plan, r_ln2_g + l*HH, r_ln2_b + l*HH, p_y);
        run_gemm(p_y, r_w1 + (size_t)l*4*HH*HH, NB*NP, 4*HH, HH, 4,
                 r_b1 + l*4*HH, nullptr, p_ffn, 1, p_part);                             // 256 blocks
        run_gemm(p_ffn, r_w2 + (size_t)l*HH*4*HH, NB*NP, HH, 4*HH, 16,
                 r_b2 + l*HH, p_plan, p_plan, 0, p_part);                               // 256 blocks
    }

    // 6) outputs
    int ncopy = out_size < PLAN_ELEMS ? out_size : PLAN_ELEMS;
    copy_plan_kernel<<<(ncopy + 255) / 256, 256>>>(out, ncopy);
    red_kernel<<<16, 128>>>();
    finalize_kernel<<<1, 256>>>(out, out_size);
}